// round 14
// baseline (speedup 1.0000x reference)
#include <cuda_runtime.h>
#include <cuda_bf16.h>
#include <stdint.h>

// ---------------- problem constants ----------------
#define N_NODES 16384
#define NE      524288
#define IN_F    128
#define OUT_F   64
#define N_TILES 16512   // sum over ti of (256 - 2*ti)

// ---------------- device scratch ----------------
__device__ float         g_hw [N_NODES * OUT_F];   // 4 MB
__device__ float         g_agg[N_NODES * OUT_F];   // 4 MB
__device__ __nv_bfloat16 g_xhi[N_NODES * OUT_F];   // 2 MB
__device__ __nv_bfloat16 g_xlo[N_NODES * OUT_F];   // 2 MB
__device__ int           g_is64;

// ---------------- launch 1: fused proj + zero(agg) + detect ----------------
__global__ __launch_bounds__(256) void k_fused1(const float* __restrict__ h,
                                                const float* __restrict__ W,
                                                const unsigned int* __restrict__ srcw) {
    int bid = blockIdx.x;
    int tid = threadIdx.x;
    if (bid < 2048) {
        __shared__ float sW[IN_F * OUT_F];
        __shared__ float sH[8][IN_F];
        int wid = tid >> 5, lid = tid & 31;
        for (int i = tid; i < IN_F * OUT_F; i += 256) sW[i] = W[i];
        int r = bid * 8 + wid;
        #pragma unroll
        for (int t = 0; t < 4; t++) sH[wid][lid + 32 * t] = h[(size_t)r * IN_F + lid + 32 * t];
        __syncthreads();
        float a0 = 0.f, a1 = 0.f;
        #pragma unroll
        for (int k = 0; k < IN_F; k++) {
            float hv = sH[wid][k];
            a0 += hv * sW[k * OUT_F + lid];
            a1 += hv * sW[k * OUT_F + lid + 32];
        }
        g_hw[r * OUT_F + lid]      = a0;
        g_hw[r * OUT_F + lid + 32] = a1;
    } else if (bid < 6144) {
        int i = (bid - 2048) * 256 + tid;
        g_agg[i] = 0.f;
    } else {
        __shared__ int cnt;
        if (tid == 0) cnt = 0;
        __syncthreads();
        int z = 0;
        for (int i = tid; i < 1024; i += 256)
            z += (srcw[2 * i + 1] == 0u) ? 1 : 0;
        atomicAdd(&cnt, z);
        __syncthreads();
        if (tid == 0) g_is64 = (cnt > 512) ? 1 : 0;
    }
}

// ---------------- launch 2: scatter, 2 edges per 16-lane group ----------------
__global__ __launch_bounds__(256) void k2_scatter(const unsigned int* __restrict__ srcw,
                                                  const unsigned int* __restrict__ dstw) {
    unsigned g = (blockIdx.x * 256u + threadIdx.x) >> 4;
    int sub = threadIdx.x & 15;
    unsigned s0, s1, d0, d1;
    if (!g_is64) {
        uint2 sv = *(const uint2*)&srcw[2 * (size_t)g];
        uint2 dv = *(const uint2*)&dstw[2 * (size_t)g];
        s0 = sv.x; s1 = sv.y; d0 = dv.x; d1 = dv.y;
    } else {
        uint4 sv = *(const uint4*)&srcw[4 * (size_t)g];
        uint4 dv = *(const uint4*)&dstw[4 * (size_t)g];
        s0 = sv.x; s1 = sv.z; d0 = dv.x; d1 = dv.z;
    }
    const float4* src = (const float4*)g_hw;
    float4 v0 = src[s0 * 16 + sub];
    asm volatile("red.global.add.v4.f32 [%0], {%1,%2,%3,%4};"
                 :: "l"(&g_agg[d0 * OUT_F + sub * 4]),
                    "f"(v0.x), "f"(v0.y), "f"(v0.z), "f"(v0.w) : "memory");
    float4 v1 = src[s1 * 16 + sub];
    asm volatile("red.global.add.v4.f32 [%0], {%1,%2,%3,%4};"
                 :: "l"(&g_agg[d1 * OUT_F + sub * 4]),
                    "f"(v1.x), "f"(v1.y), "f"(v1.z), "f"(v1.w) : "memory");
}

// ---------------- threefry2x32 (JAX-exact, 20 rounds) ----------------
__device__ __forceinline__ void threefry2x32(uint32_t k0, uint32_t k1,
                                             uint32_t x0, uint32_t x1,
                                             uint32_t& o0, uint32_t& o1) {
    uint32_t ks0 = k0, ks1 = k1, ks2 = 0x1BD11BDAu ^ k0 ^ k1;
    x0 += ks0; x1 += ks1;
#define TF_R(rr) { x0 += x1; x1 = (x1 << (rr)) | (x1 >> (32 - (rr))); x1 ^= x0; }
    TF_R(13) TF_R(15) TF_R(26) TF_R(6)  x0 += ks1; x1 += ks2 + 1u;
    TF_R(17) TF_R(29) TF_R(16) TF_R(24) x0 += ks2; x1 += ks0 + 2u;
    TF_R(13) TF_R(15) TF_R(26) TF_R(6)  x0 += ks0; x1 += ks1 + 3u;
    TF_R(17) TF_R(29) TF_R(16) TF_R(24) x0 += ks1; x1 += ks2 + 4u;
    TF_R(13) TF_R(15) TF_R(26) TF_R(6)  x0 += ks2; x1 += ks0 + 5u;
#undef TF_R
    o0 = x0; o1 = x1;
}

// ---------------- launch 3: relu + dropout mask + bf16 hi/lo split ----------------
__global__ __launch_bounds__(256) void k3_mask(const float* __restrict__ bias) {
    int i = blockIdx.x * 256 + threadIdx.x;
    uint32_t o0, o1;
    threefry2x32(0u, 42u, 0u, (uint32_t)i, o0, o1);
    uint32_t bits = o0 ^ o1;
    float u = __uint_as_float((bits >> 9) | 0x3f800000u) - 1.0f;
    float v = g_agg[i] + bias[i & 63];
    v = fmaxf(v, 0.0f);
    float y = (u < 0.7f) ? (v / 0.7f) : 0.0f;
    __nv_bfloat16 hi = __float2bfloat16(y);
    g_xhi[i] = hi;
    g_xlo[i] = __float2bfloat16(y - __bfloat162float(hi));
}

// ---------------- launch 4: out = x @ x^T, triangular 128x64 tiles, 4 CTA/SM ----------
// Tile (ti,cj), cj >= 2*ti: rows [ti*128,+128) x cols [cj*64,+64). Writes direct tile
// and its transpose (async bulk S2G). Diagonal-straddling tiles double-write consistent
// values (<=1 ulp). 256 threads, 4x2 warp grid, 48KB smem -> 4 CTAs/SM.
#define SM_AHI  0
#define SM_ALO  16384
#define SM_BHI  32768
#define SM_BLO  40960
#define SM_TOTAL 49152
#define STG_D 72    // direct stage stride (floats): 128 x 72 x 4 = 36864 B
#define STG_T 136   // transposed stage stride:       64 x 136 x 4 = 34816 B

__device__ __forceinline__ void ldsm_x4(uint32_t* r, uint32_t addr) {
    asm volatile("ldmatrix.sync.aligned.m8n8.x4.shared.b16 {%0,%1,%2,%3}, [%4];"
                 : "=r"(r[0]), "=r"(r[1]), "=r"(r[2]), "=r"(r[3]) : "r"(addr));
}
__device__ __forceinline__ void mma16816(float* d, const uint32_t* a,
                                         uint32_t b0, uint32_t b1) {
    asm volatile(
        "mma.sync.aligned.m16n8k16.row.col.f32.bf16.bf16.f32 "
        "{%0,%1,%2,%3}, {%4,%5,%6,%7}, {%8,%9}, {%0,%1,%2,%3};"
        : "+f"(d[0]), "+f"(d[1]), "+f"(d[2]), "+f"(d[3])
        : "r"(a[0]), "r"(a[1]), "r"(a[2]), "r"(a[3]), "r"(b0), "r"(b1));
}
__device__ __forceinline__ void cp_async16(uint32_t saddr, const void* gptr) {
    asm volatile("cp.async.cg.shared.global [%0], [%1], 16;"
                 :: "r"(saddr), "l"(gptr) : "memory");
}
__device__ __forceinline__ void bulk_store(void* gptr, uint32_t saddr, unsigned bytes) {
    asm volatile("cp.async.bulk.global.shared::cta.bulk_group [%0], [%1], %2;"
                 :: "l"(gptr), "r"(saddr), "r"(bytes) : "memory");
}

__global__ __launch_bounds__(256, 4)
void k4_gemm(float* __restrict__ out) {
    extern __shared__ char smem[];
    uint32_t sb = (uint32_t)__cvta_generic_to_shared(smem);
    int tid = threadIdx.x, wid = tid >> 5, lid = tid & 31;
    int wm = wid & 3, wn = wid >> 2;   // 4x2 warp grid; warp tile 32 rows x 32 cols

    // decode bid -> (ti, cj), cj >= 2*ti ; off(t) = t*(257 - t)
    int bid = blockIdx.x;
    int ti = (int)((257.0 - sqrt(257.0 * 257.0 - 4.0 * (double)bid)) * 0.5);
    if (ti < 0) ti = 0;
    while ((ti + 1) * (257 - (ti + 1)) <= bid) ti++;
    while (ti * (257 - ti) > bid) ti--;
    int cj = 2 * ti + (bid - ti * (257 - ti));
    int rowA = ti << 7;   // 128 rows
    int colB = cj << 6;   // 64 cols

    // ---- prologue: cp.async operand tiles with SW128 swizzle ----
    {
        const char* pAh = (const char*)(g_xhi + (size_t)rowA * OUT_F);
        const char* pAl = (const char*)(g_xlo + (size_t)rowA * OUT_F);
        const char* pBh = (const char*)(g_xhi + (size_t)colB * OUT_F);
        const char* pBl = (const char*)(g_xlo + (size_t)colB * OUT_F);
        #pragma unroll
        for (int j = 0; j < 4; j++) {
            int idx = tid + j * 256;                 // A: 1024 chunks each
            uint32_t bo = (uint32_t)(idx << 4);
            uint32_t sw = bo ^ ((bo >> 3) & 0x70);
            cp_async16(sb + SM_AHI + sw, pAh + ((size_t)idx << 4));
            cp_async16(sb + SM_ALO + sw, pAl + ((size_t)idx << 4));
        }
        #pragma unroll
        for (int j = 0; j < 2; j++) {
            int idx = tid + j * 256;                 // B: 512 chunks each
            uint32_t bo = (uint32_t)(idx << 4);
            uint32_t sw = bo ^ ((bo >> 3) & 0x70);
            cp_async16(sb + SM_BHI + sw, pBh + ((size_t)idx << 4));
            cp_async16(sb + SM_BLO + sw, pBl + ((size_t)idx << 4));
        }
        asm volatile("cp.async.commit_group;" ::: "memory");
        asm volatile("cp.async.wait_group 0;" ::: "memory");
    }
    __syncthreads();

    float acc[2][4][4];
    #pragma unroll
    for (int mt = 0; mt < 2; mt++)
        #pragma unroll
        for (int nt = 0; nt < 4; nt++)
            #pragma unroll
            for (int e = 0; e < 4; e++) acc[mt][nt][e] = 0.f;

    int lrow = lid & 15, lchk = lid >> 4, lswz = lid & 7;

    #pragma unroll
    for (int kc = 0; kc < 4; kc++) {
        uint32_t chunk = (uint32_t)(((2 * kc + lchk) ^ lswz) << 4);
        uint32_t ah[2][4], al[2][4];
        #pragma unroll
        for (int mt = 0; mt < 2; mt++) {
            uint32_t ro = (uint32_t)((wm * 32 + mt * 16 + lrow) * 128) + chunk;
            ldsm_x4(ah[mt], sb + SM_AHI + ro);
            ldsm_x4(al[mt], sb + SM_ALO + ro);
        }
        #pragma unroll
        for (int np = 0; np < 2; np++) {
            uint32_t bh[4], bl[4];
            uint32_t ro = (uint32_t)((wn * 32 + np * 16 + lrow) * 128) + chunk;
            ldsm_x4(bh, sb + SM_BHI + ro);
            ldsm_x4(bl, sb + SM_BLO + ro);
            #pragma unroll
            for (int mt = 0; mt < 2; mt++)
                #pragma unroll
                for (int sel = 0; sel < 2; sel++) {
                    int nt = np * 2 + sel;
                    mma16816(acc[mt][nt], ah[mt], bh[sel], bh[sel + 2]); // hi*hi
                    mma16816(acc[mt][nt], ah[mt], bl[sel], bl[sel + 2]); // hi*lo
                    mma16816(acc[mt][nt], al[mt], bh[sel], bh[sel + 2]); // lo*hi
                }
        }
    }
    __syncthreads();   // operands dead; reuse smem as stage

    float* stage = (float*)smem;
    int gid = lid >> 2, tig = lid & 3;

    // ---- pass 1: direct tile (128 x 64) -> stage(STG_D) -> bulk rows of 256 B ----
    #pragma unroll
    for (int mt = 0; mt < 2; mt++)
        #pragma unroll
        for (int half = 0; half < 2; half++) {
            int r = wm * 32 + mt * 16 + gid + 8 * half;
            #pragma unroll
            for (int nt = 0; nt < 4; nt++) {
                int c = wn * 32 + nt * 8 + tig * 2;
                *(float2*)&stage[r * STG_D + c] =
                    make_float2(acc[mt][nt][half * 2], acc[mt][nt][half * 2 + 1]);
            }
        }
    __syncthreads();
    if (tid < 128) {
        asm volatile("fence.proxy.async.shared::cta;" ::: "memory");
        bulk_store(out + (size_t)(rowA + tid) * 16384 + colB,
                   sb + (uint32_t)(tid * STG_D * 4), 256u);
        asm volatile("cp.async.bulk.commit_group;" ::: "memory");
    }

    // ---- pass 2: transposed tile (64 x 128) -> stage(STG_T) -> bulk rows of 512 B ----
    asm volatile("cp.async.bulk.wait_group 0;" ::: "memory");   // stage reusable
    __syncthreads();
    #pragma unroll
    for (int mt = 0; mt < 2; mt++)
        #pragma unroll
        for (int half = 0; half < 2; half++) {
            int r = wm * 32 + mt * 16 + gid + 8 * half;
            #pragma unroll
            for (int nt = 0; nt < 4; nt++) {
                int c = wn * 32 + nt * 8 + tig * 2;
                stage[c * STG_T + r]       = acc[mt][nt][half * 2];
                stage[(c + 1) * STG_T + r] = acc[mt][nt][half * 2 + 1];
            }
        }
    __syncthreads();
    if (tid < 64) {
        asm volatile("fence.proxy.async.shared::cta;" ::: "memory");
        bulk_store(out + (size_t)(colB + tid) * 16384 + rowA,
                   sb + (uint32_t)(tid * STG_T * 4), 512u);
        asm volatile("cp.async.bulk.commit_group;" ::: "memory");
        asm volatile("cp.async.bulk.wait_group 0;" ::: "memory");
    }
}

// ---------------- launch ----------------
extern "C" void kernel_launch(void* const* d_in, const int* in_sizes, int n_in,
                              void* d_out, int out_size) {
    const float*        h    = (const float*)d_in[0];
    const unsigned int* srcw = (const unsigned int*)d_in[1];
    const unsigned int* dstw = (const unsigned int*)d_in[2];
    const float*        W    = (const float*)d_in[3];
    const float*        bias = (const float*)d_in[4];
    float*              out  = (float*)d_out;

    k_fused1<<<6145, 256>>>(h, W, srcw);                    // 1
    k2_scatter<<<(NE / 2 * 16) / 256, 256>>>(srcw, dstw);   // 2
    k3_mask<<<(N_NODES * OUT_F) / 256, 256>>>(bias);        // 3

    cudaFuncSetAttribute(k4_gemm, cudaFuncAttributeMaxDynamicSharedMemorySize, SM_TOTAL);
    k4_gemm<<<N_TILES, 256, SM_TOTAL>>>(out);               // 4 (ncu target)
}

// round 15
// speedup vs baseline: 1.0020x; 1.0020x over previous
#include <cuda_runtime.h>
#include <cuda_bf16.h>
#include <stdint.h>

// ---------------- problem constants ----------------
#define N_NODES 16384
#define NE      524288
#define IN_F    128
#define OUT_F   64
#define NB      256                       // 64-row blocks
#define N_TILES ((NB * (NB + 1)) / 2)     // 32896 triangular 64x64 tiles

// ---------------- device scratch ----------------
__device__ float         g_hw [N_NODES * OUT_F];   // 4 MB
__device__ float         g_agg[N_NODES * OUT_F];   // 4 MB
__device__ __nv_bfloat16 g_xhi[N_NODES * OUT_F];   // 2 MB
__device__ __nv_bfloat16 g_xlo[N_NODES * OUT_F];   // 2 MB
__device__ int           g_is64;

// ---------------- launch 1: fused proj + zero(agg) + detect ----------------
__global__ __launch_bounds__(256) void k_fused1(const float* __restrict__ h,
                                                const float* __restrict__ W,
                                                const unsigned int* __restrict__ srcw) {
    int bid = blockIdx.x;
    int tid = threadIdx.x;
    if (bid < 2048) {
        __shared__ float sW[IN_F * OUT_F];
        __shared__ float sH[8][IN_F];
        int wid = tid >> 5, lid = tid & 31;
        for (int i = tid; i < IN_F * OUT_F; i += 256) sW[i] = W[i];
        int r = bid * 8 + wid;
        #pragma unroll
        for (int t = 0; t < 4; t++) sH[wid][lid + 32 * t] = h[(size_t)r * IN_F + lid + 32 * t];
        __syncthreads();
        float a0 = 0.f, a1 = 0.f;
        #pragma unroll
        for (int k = 0; k < IN_F; k++) {
            float hv = sH[wid][k];
            a0 += hv * sW[k * OUT_F + lid];
            a1 += hv * sW[k * OUT_F + lid + 32];
        }
        g_hw[r * OUT_F + lid]      = a0;
        g_hw[r * OUT_F + lid + 32] = a1;
    } else if (bid < 6144) {
        int i = (bid - 2048) * 256 + tid;
        g_agg[i] = 0.f;
    } else {
        __shared__ int cnt;
        if (tid == 0) cnt = 0;
        __syncthreads();
        int z = 0;
        for (int i = tid; i < 1024; i += 256)
            z += (srcw[2 * i + 1] == 0u) ? 1 : 0;
        atomicAdd(&cnt, z);
        __syncthreads();
        if (tid == 0) g_is64 = (cnt > 512) ? 1 : 0;
    }
}

// ---------------- launch 2: scatter, 2 edges per 16-lane group ----------------
__global__ __launch_bounds__(256) void k2_scatter(const unsigned int* __restrict__ srcw,
                                                  const unsigned int* __restrict__ dstw) {
    unsigned g = (blockIdx.x * 256u + threadIdx.x) >> 4;
    int sub = threadIdx.x & 15;
    unsigned s0, s1, d0, d1;
    if (!g_is64) {
        uint2 sv = *(const uint2*)&srcw[2 * (size_t)g];
        uint2 dv = *(const uint2*)&dstw[2 * (size_t)g];
        s0 = sv.x; s1 = sv.y; d0 = dv.x; d1 = dv.y;
    } else {
        uint4 sv = *(const uint4*)&srcw[4 * (size_t)g];
        uint4 dv = *(const uint4*)&dstw[4 * (size_t)g];
        s0 = sv.x; s1 = sv.z; d0 = dv.x; d1 = dv.z;
    }
    const float4* src = (const float4*)g_hw;
    float4 v0 = src[s0 * 16 + sub];
    asm volatile("red.global.add.v4.f32 [%0], {%1,%2,%3,%4};"
                 :: "l"(&g_agg[d0 * OUT_F + sub * 4]),
                    "f"(v0.x), "f"(v0.y), "f"(v0.z), "f"(v0.w) : "memory");
    float4 v1 = src[s1 * 16 + sub];
    asm volatile("red.global.add.v4.f32 [%0], {%1,%2,%3,%4};"
                 :: "l"(&g_agg[d1 * OUT_F + sub * 4]),
                    "f"(v1.x), "f"(v1.y), "f"(v1.z), "f"(v1.w) : "memory");
}

// ---------------- threefry2x32 (JAX-exact, 20 rounds) ----------------
__device__ __forceinline__ void threefry2x32(uint32_t k0, uint32_t k1,
                                             uint32_t x0, uint32_t x1,
                                             uint32_t& o0, uint32_t& o1) {
    uint32_t ks0 = k0, ks1 = k1, ks2 = 0x1BD11BDAu ^ k0 ^ k1;
    x0 += ks0; x1 += ks1;
#define TF_R(rr) { x0 += x1; x1 = (x1 << (rr)) | (x1 >> (32 - (rr))); x1 ^= x0; }
    TF_R(13) TF_R(15) TF_R(26) TF_R(6)  x0 += ks1; x1 += ks2 + 1u;
    TF_R(17) TF_R(29) TF_R(16) TF_R(24) x0 += ks2; x1 += ks0 + 2u;
    TF_R(13) TF_R(15) TF_R(26) TF_R(6)  x0 += ks0; x1 += ks1 + 3u;
    TF_R(17) TF_R(29) TF_R(16) TF_R(24) x0 += ks1; x1 += ks2 + 4u;
    TF_R(13) TF_R(15) TF_R(26) TF_R(6)  x0 += ks2; x1 += ks0 + 5u;
#undef TF_R
    o0 = x0; o1 = x1;
}

// ---------------- launch 3: relu + dropout mask + bf16 hi/lo split ----------------
__global__ __launch_bounds__(256) void k3_mask(const float* __restrict__ bias) {
    int i = blockIdx.x * 256 + threadIdx.x;
    uint32_t o0, o1;
    threefry2x32(0u, 42u, 0u, (uint32_t)i, o0, o1);
    uint32_t bits = o0 ^ o1;
    float u = __uint_as_float((bits >> 9) | 0x3f800000u) - 1.0f;
    float v = g_agg[i] + bias[i & 63];
    v = fmaxf(v, 0.0f);
    float y = (u < 0.7f) ? (v / 0.7f) : 0.0f;
    __nv_bfloat16 hi = __float2bfloat16(y);
    g_xhi[i] = hi;
    g_xlo[i] = __float2bfloat16(y - __bfloat162float(hi));
}

// ---------------- launch 4: out = x @ x^T, triangular 64x64 tiles, 7 CTA/SM -----------
// Tile (ci<=cj): rows [ci*64,+64) x cols [cj*64,+64). 128 threads, 2x2 warp grid of
// 32x32 warp tiles. Bulk async S2G stores for direct + transposed passes.
#define SM_AHI  0
#define SM_ALO  8192
#define SM_BHI  16384
#define SM_BLO  24576
#define SM_TOTAL 32768
#define STG_S 68    // stage stride (floats): 64 x 68 x 4 = 17408 B (reuses operand smem)

__device__ __forceinline__ void ldsm_x4(uint32_t* r, uint32_t addr) {
    asm volatile("ldmatrix.sync.aligned.m8n8.x4.shared.b16 {%0,%1,%2,%3}, [%4];"
                 : "=r"(r[0]), "=r"(r[1]), "=r"(r[2]), "=r"(r[3]) : "r"(addr));
}
__device__ __forceinline__ void mma16816(float* d, const uint32_t* a,
                                         uint32_t b0, uint32_t b1) {
    asm volatile(
        "mma.sync.aligned.m16n8k16.row.col.f32.bf16.bf16.f32 "
        "{%0,%1,%2,%3}, {%4,%5,%6,%7}, {%8,%9}, {%0,%1,%2,%3};"
        : "+f"(d[0]), "+f"(d[1]), "+f"(d[2]), "+f"(d[3])
        : "r"(a[0]), "r"(a[1]), "r"(a[2]), "r"(a[3]), "r"(b0), "r"(b1));
}
__device__ __forceinline__ void cp_async16(uint32_t saddr, const void* gptr) {
    asm volatile("cp.async.cg.shared.global [%0], [%1], 16;"
                 :: "r"(saddr), "l"(gptr) : "memory");
}
__device__ __forceinline__ void bulk_store(void* gptr, uint32_t saddr, unsigned bytes) {
    asm volatile("cp.async.bulk.global.shared::cta.bulk_group [%0], [%1], %2;"
                 :: "l"(gptr), "r"(saddr), "r"(bytes) : "memory");
}

__global__ __launch_bounds__(128, 7)
void k4_gemm(float* __restrict__ out) {
    extern __shared__ char smem[];
    uint32_t sb = (uint32_t)__cvta_generic_to_shared(smem);
    int tid = threadIdx.x, wid = tid >> 5, lid = tid & 31;
    int wm = wid & 1, wn = wid >> 1;   // 2x2 warp grid; warp tile 32 rows x 32 cols

    // decode bid -> (ci <= cj); off(c) = c*(513-c)/2
    int bid = blockIdx.x;
    int ci = (int)((513.0 - sqrt(513.0 * 513.0 - 8.0 * (double)bid)) * 0.5);
    if (ci < 0) ci = 0;
    if (ci > 255) ci = 255;
    while (ci < 255 && (ci + 1) * (513 - (ci + 1)) / 2 <= bid) ci++;
    while (ci > 0 && ci * (513 - ci) / 2 > bid) ci--;
    int cj = ci + (bid - ci * (513 - ci) / 2);
    int rowA = ci << 6;   // 64 rows
    int colB = cj << 6;   // 64 cols

    // ---- prologue: cp.async operand slabs (each 64 rows x 128 B) with SW128 swizzle ----
    {
        const char* pAh = (const char*)(g_xhi + (size_t)rowA * OUT_F);
        const char* pAl = (const char*)(g_xlo + (size_t)rowA * OUT_F);
        const char* pBh = (const char*)(g_xhi + (size_t)colB * OUT_F);
        const char* pBl = (const char*)(g_xlo + (size_t)colB * OUT_F);
        #pragma unroll
        for (int j = 0; j < 4; j++) {
            int idx = tid + j * 128;                 // 512 chunks per slab
            uint32_t bo = (uint32_t)(idx << 4);
            uint32_t sw = bo ^ ((bo >> 3) & 0x70);
            cp_async16(sb + SM_AHI + sw, pAh + ((size_t)idx << 4));
            cp_async16(sb + SM_ALO + sw, pAl + ((size_t)idx << 4));
            cp_async16(sb + SM_BHI + sw, pBh + ((size_t)idx << 4));
            cp_async16(sb + SM_BLO + sw, pBl + ((size_t)idx << 4));
        }
        asm volatile("cp.async.commit_group;" ::: "memory");
        asm volatile("cp.async.wait_group 0;" ::: "memory");
    }
    __syncthreads();

    float acc[2][4][4];
    #pragma unroll
    for (int mt = 0; mt < 2; mt++)
        #pragma unroll
        for (int nt = 0; nt < 4; nt++)
            #pragma unroll
            for (int e = 0; e < 4; e++) acc[mt][nt][e] = 0.f;

    int lrow = lid & 15, lchk = lid >> 4, lswz = lid & 7;

    #pragma unroll
    for (int kc = 0; kc < 4; kc++) {
        uint32_t chunk = (uint32_t)(((2 * kc + lchk) ^ lswz) << 4);
        uint32_t ah[2][4], al[2][4];
        #pragma unroll
        for (int mt = 0; mt < 2; mt++) {
            uint32_t ro = (uint32_t)((wm * 32 + mt * 16 + lrow) * 128) + chunk;
            ldsm_x4(ah[mt], sb + SM_AHI + ro);
            ldsm_x4(al[mt], sb + SM_ALO + ro);
        }
        #pragma unroll
        for (int np = 0; np < 2; np++) {
            uint32_t bh[4], bl[4];
            uint32_t ro = (uint32_t)((wn * 32 + np * 16 + lrow) * 128) + chunk;
            ldsm_x4(bh, sb + SM_BHI + ro);
            ldsm_x4(bl, sb + SM_BLO + ro);
            #pragma unroll
            for (int mt = 0; mt < 2; mt++)
                #pragma unroll
                for (int sel = 0; sel < 2; sel++) {
                    int nt = np * 2 + sel;
                    mma16816(acc[mt][nt], ah[mt], bh[sel], bh[sel + 2]); // hi*hi
                    mma16816(acc[mt][nt], ah[mt], bl[sel], bl[sel + 2]); // hi*lo
                    mma16816(acc[mt][nt], al[mt], bh[sel], bh[sel + 2]); // lo*hi
                }
        }
    }
    __syncthreads();   // operands dead; reuse smem as stage

    float* stage = (float*)smem;     // [64][STG_S]
    int gid = lid >> 2, tig = lid & 3;

    // ---- pass 1: direct tile (64 x 64) -> stage -> bulk rows of 256 B ----
    #pragma unroll
    for (int mt = 0; mt < 2; mt++)
        #pragma unroll
        for (int half = 0; half < 2; half++) {
            int r = wm * 32 + mt * 16 + gid + 8 * half;
            #pragma unroll
            for (int nt = 0; nt < 4; nt++) {
                int c = wn * 32 + nt * 8 + tig * 2;
                *(float2*)&stage[r * STG_S + c] =
                    make_float2(acc[mt][nt][half * 2], acc[mt][nt][half * 2 + 1]);
            }
        }
    __syncthreads();
    if (tid < 64) {
        asm volatile("fence.proxy.async.shared::cta;" ::: "memory");
        bulk_store(out + (size_t)(rowA + tid) * 16384 + colB,
                   sb + (uint32_t)(tid * STG_S * 4), 256u);
        asm volatile("cp.async.bulk.commit_group;" ::: "memory");
    }

    // ---- pass 2: transposed tile (skip on diagonal) ----
    if (ci != cj) {
        if (tid < 64)
            asm volatile("cp.async.bulk.wait_group 0;" ::: "memory");   // stage reusable
        __syncthreads();
        #pragma unroll
        for (int mt = 0; mt < 2; mt++)
            #pragma unroll
            for (int half = 0; half < 2; half++) {
                int r = wm * 32 + mt * 16 + gid + 8 * half;
                #pragma unroll
                for (int nt = 0; nt < 4; nt++) {
                    int c = wn * 32 + nt * 8 + tig * 2;
                    stage[c * STG_S + r]       = acc[mt][nt][half * 2];
                    stage[(c + 1) * STG_S + r] = acc[mt][nt][half * 2 + 1];
                }
            }
        __syncthreads();
        if (tid < 64) {
            asm volatile("fence.proxy.async.shared::cta;" ::: "memory");
            bulk_store(out + (size_t)(colB + tid) * 16384 + rowA,
                       sb + (uint32_t)(tid * STG_S * 4), 256u);
            asm volatile("cp.async.bulk.commit_group;" ::: "memory");
        }
    }

    // drain before CTA exit
    if (tid < 64)
        asm volatile("cp.async.bulk.wait_group 0;" ::: "memory");
}

// ---------------- launch ----------------
extern "C" void kernel_launch(void* const* d_in, const int* in_sizes, int n_in,
                              void* d_out, int out_size) {
    const float*        h    = (const float*)d_in[0];
    const unsigned int* srcw = (const unsigned int*)d_in[1];
    const unsigned int* dstw = (const unsigned int*)d_in[2];
    const float*        W    = (const float*)d_in[3];
    const float*        bias = (const float*)d_in[4];
    float*              out  = (float*)d_out;

    k_fused1<<<6145, 256>>>(h, W, srcw);                    // 1
    k2_scatter<<<(NE / 2 * 16) / 256, 256>>>(srcw, dstw);   // 2
    k3_mask<<<(N_NODES * OUT_F) / 256, 256>>>(bias);        // 3

    cudaFuncSetAttribute(k4_gemm, cudaFuncAttributeMaxDynamicSharedMemorySize, SM_TOTAL);
    k4_gemm<<<N_TILES, 128, SM_TOTAL>>>(out);               // 4 (ncu target)
}

// round 16
// speedup vs baseline: 1.0618x; 1.0597x over previous
#include <cuda_runtime.h>
#include <cuda_bf16.h>
#include <stdint.h>

// ---------------- problem constants ----------------
#define N_NODES 16384
#define NE      524288
#define IN_F    128
#define OUT_F   64
#define NB      256                       // 64-row blocks
#define N_TILES ((NB * (NB + 1)) / 2)     // 32896 triangular 64x64 tiles

// ---------------- device scratch ----------------
__device__ float         g_hw [N_NODES * OUT_F];   // 4 MB
__device__ float         g_agg[N_NODES * OUT_F];   // 4 MB
__device__ __nv_bfloat16 g_xhi[N_NODES * OUT_F];   // 2 MB
__device__ __nv_bfloat16 g_xlo[N_NODES * OUT_F];   // 2 MB
__device__ int           g_is64;

// ---------------- shared mma helpers ----------------
__device__ __forceinline__ void ldsm_x4(uint32_t* r, uint32_t addr) {
    asm volatile("ldmatrix.sync.aligned.m8n8.x4.shared.b16 {%0,%1,%2,%3}, [%4];"
                 : "=r"(r[0]), "=r"(r[1]), "=r"(r[2]), "=r"(r[3]) : "r"(addr));
}
__device__ __forceinline__ void mma16816(float* d, const uint32_t* a,
                                         uint32_t b0, uint32_t b1) {
    asm volatile(
        "mma.sync.aligned.m16n8k16.row.col.f32.bf16.bf16.f32 "
        "{%0,%1,%2,%3}, {%4,%5,%6,%7}, {%8,%9}, {%0,%1,%2,%3};"
        : "+f"(d[0]), "+f"(d[1]), "+f"(d[2]), "+f"(d[3])
        : "r"(a[0]), "r"(a[1]), "r"(a[2]), "r"(a[3]), "r"(b0), "r"(b1));
}
__device__ __forceinline__ void cp_async16(uint32_t saddr, const void* gptr) {
    asm volatile("cp.async.cg.shared.global [%0], [%1], 16;"
                 :: "r"(saddr), "l"(gptr) : "memory");
}
__device__ __forceinline__ void bulk_store(void* gptr, uint32_t saddr, unsigned bytes) {
    asm volatile("cp.async.bulk.global.shared::cta.bulk_group [%0], [%1], %2;"
                 :: "l"(gptr), "r"(saddr), "r"(bytes) : "memory");
}

// ---------------- launch 1: fused tensor-proj + zero(agg) + detect ----------------
// bids [0,256): proj 64-row tiles via bf16 hi/lo mma (3 products, err ~2^-16)
// bids [256,2304): zero g_agg (512 floats/thread-block of 128 via float4)
// bid 2304: int-width detect
// smem: sAhi(16K) sAlo(16K) sBhi(16K) sBlo(16K); each = 2 slabs of [64 rows][128 B]
#define PJ_AHI 0
#define PJ_ALO 16384
#define PJ_BHI 32768
#define PJ_BLO 49152
#define PJ_SMEM 65536

__global__ __launch_bounds__(128) void k_fused1(const float* __restrict__ h,
                                                const float* __restrict__ W,
                                                const unsigned int* __restrict__ srcw) {
    int bid = blockIdx.x;
    int tid = threadIdx.x;
    if (bid >= 256) {
        if (bid < 2304) {
            int i = ((bid - 256) * 128 + tid) * 4;
            *(float4*)&g_agg[i] = make_float4(0.f, 0.f, 0.f, 0.f);
        } else {
            __shared__ int cnt;
            if (tid == 0) cnt = 0;
            __syncthreads();
            int z = 0;
            for (int i = tid; i < 1024; i += 128)
                z += (srcw[2 * i + 1] == 0u) ? 1 : 0;
            atomicAdd(&cnt, z);
            __syncthreads();
            if (tid == 0) g_is64 = (cnt > 512) ? 1 : 0;
            return;
        }
        return;
    }

    extern __shared__ char smem[];
    uint32_t sb = (uint32_t)__cvta_generic_to_shared(smem);
    int wid = tid >> 5, lid = tid & 31;
    int wm = wid & 1, wn = wid >> 1;       // 2x2 warp grid; warp tile 32 rows x 32 cols
    int row0 = bid * 64;

    // ---- stage h rows (64 x 128 fp32) as bf16 hi/lo, 2-slab SW128 ----
    {
        // 8192 elements, 64 per thread (float4 chunks: 2048 total, 16/thread)
        const float4* hp = (const float4*)(h + (size_t)row0 * IN_F);
        #pragma unroll
        for (int j = 0; j < 16; j++) {
            int ci = tid + j * 128;          // float4 index; 32 per row
            float4 v = hp[ci];
            int r = ci >> 5, k4i = (ci & 31) << 2;
            #pragma unroll
            for (int e = 0; e < 4; e++) {
                float f = (&v.x)[e];
                int k = k4i + e;
                __nv_bfloat16 hi = __float2bfloat16(f);
                __nv_bfloat16 lo = __float2bfloat16(f - __bfloat162float(hi));
                uint32_t off = (uint32_t)((k >> 6) * 8192 + r * 128 + (k & 63) * 2);
                uint32_t sw = off ^ ((off >> 3) & 0x70);
                *(__nv_bfloat16*)(smem + PJ_AHI + sw) = hi;
                *(__nv_bfloat16*)(smem + PJ_ALO + sw) = lo;
            }
        }
        // W [128k x 64n] -> B operand [n rows][k cols], bf16 hi/lo, same layout
        const float4* wp = (const float4*)W;
        #pragma unroll
        for (int j = 0; j < 16; j++) {
            int ci = tid + j * 128;          // float4 index; 16 per k-row
            float4 v = wp[ci];
            int k = ci >> 4, n4 = (ci & 15) << 2;
            #pragma unroll
            for (int e = 0; e < 4; e++) {
                float f = (&v.x)[e];
                int n = n4 + e;
                __nv_bfloat16 hi = __float2bfloat16(f);
                __nv_bfloat16 lo = __float2bfloat16(f - __bfloat162float(hi));
                uint32_t off = (uint32_t)((k >> 6) * 8192 + n * 128 + (k & 63) * 2);
                uint32_t sw = off ^ ((off >> 3) & 0x70);
                *(__nv_bfloat16*)(smem + PJ_BHI + sw) = hi;
                *(__nv_bfloat16*)(smem + PJ_BLO + sw) = lo;
            }
        }
    }
    __syncthreads();

    float acc[2][4][4];
    #pragma unroll
    for (int mt = 0; mt < 2; mt++)
        #pragma unroll
        for (int nt = 0; nt < 4; nt++)
            #pragma unroll
            for (int e = 0; e < 4; e++) acc[mt][nt][e] = 0.f;

    int lrow = lid & 15, lchk = lid >> 4, lswz = lid & 7;

    #pragma unroll
    for (int kc = 0; kc < 8; kc++) {
        uint32_t slab = (uint32_t)((kc >> 2) * 8192);
        uint32_t chunk = (uint32_t)(((2 * (kc & 3) + lchk) ^ lswz) << 4) + slab;
        uint32_t ah[2][4], al[2][4];
        #pragma unroll
        for (int mt = 0; mt < 2; mt++) {
            uint32_t ro = (uint32_t)((wm * 32 + mt * 16 + lrow) * 128) + chunk;
            ldsm_x4(ah[mt], sb + PJ_AHI + ro);
            ldsm_x4(al[mt], sb + PJ_ALO + ro);
        }
        #pragma unroll
        for (int np = 0; np < 2; np++) {
            uint32_t bh[4], bl[4];
            uint32_t ro = (uint32_t)((wn * 32 + np * 16 + lrow) * 128) + chunk;
            ldsm_x4(bh, sb + PJ_BHI + ro);
            ldsm_x4(bl, sb + PJ_BLO + ro);
            #pragma unroll
            for (int mt = 0; mt < 2; mt++)
                #pragma unroll
                for (int sel = 0; sel < 2; sel++) {
                    int nt = np * 2 + sel;
                    mma16816(acc[mt][nt], ah[mt], bh[sel], bh[sel + 2]); // hi*hi
                    mma16816(acc[mt][nt], ah[mt], bl[sel], bl[sel + 2]); // hi*lo
                    mma16816(acc[mt][nt], al[mt], bh[sel], bh[sel + 2]); // lo*hi
                }
        }
    }

    // direct store of hw fragments (float2 per fragment pair)
    int gid = lid >> 2, tig = lid & 3;
    #pragma unroll
    for (int mt = 0; mt < 2; mt++)
        #pragma unroll
        for (int half = 0; half < 2; half++) {
            int r = wm * 32 + mt * 16 + gid + 8 * half;
            #pragma unroll
            for (int nt = 0; nt < 4; nt++) {
                int c = wn * 32 + nt * 8 + tig * 2;
                *(float2*)&g_hw[(size_t)(row0 + r) * OUT_F + c] =
                    make_float2(acc[mt][nt][half * 2], acc[mt][nt][half * 2 + 1]);
            }
        }
}

// ---------------- launch 2: scatter, 4 edges per 16-lane group (MLP=4) ----------------
__global__ __launch_bounds__(256) void k2_scatter(const unsigned int* __restrict__ srcw,
                                                  const unsigned int* __restrict__ dstw) {
    unsigned g = (blockIdx.x * 256u + threadIdx.x) >> 4;   // quad id < NE/4
    int sub = threadIdx.x & 15;
    unsigned s[4], d[4];
    if (!g_is64) {
        uint4 sv = *(const uint4*)&srcw[4 * (size_t)g];
        uint4 dv = *(const uint4*)&dstw[4 * (size_t)g];
        s[0] = sv.x; s[1] = sv.y; s[2] = sv.z; s[3] = sv.w;
        d[0] = dv.x; d[1] = dv.y; d[2] = dv.z; d[3] = dv.w;
    } else {
        uint4 sv0 = *(const uint4*)&srcw[8 * (size_t)g];
        uint4 sv1 = *(const uint4*)&srcw[8 * (size_t)g + 4];
        uint4 dv0 = *(const uint4*)&dstw[8 * (size_t)g];
        uint4 dv1 = *(const uint4*)&dstw[8 * (size_t)g + 4];
        s[0] = sv0.x; s[1] = sv0.z; s[2] = sv1.x; s[3] = sv1.z;
        d[0] = dv0.x; d[1] = dv0.z; d[2] = dv1.x; d[3] = dv1.z;
    }
    const float4* src = (const float4*)g_hw;
    float4 v[4];
    #pragma unroll
    for (int i = 0; i < 4; i++) v[i] = src[s[i] * 16 + sub];
    #pragma unroll
    for (int i = 0; i < 4; i++)
        asm volatile("red.global.add.v4.f32 [%0], {%1,%2,%3,%4};"
                     :: "l"(&g_agg[d[i] * OUT_F + sub * 4]),
                        "f"(v[i].x), "f"(v[i].y), "f"(v[i].z), "f"(v[i].w) : "memory");
}

// ---------------- threefry2x32 (JAX-exact, 20 rounds) ----------------
__device__ __forceinline__ void threefry2x32(uint32_t k0, uint32_t k1,
                                             uint32_t x0, uint32_t x1,
                                             uint32_t& o0, uint32_t& o1) {
    uint32_t ks0 = k0, ks1 = k1, ks2 = 0x1BD11BDAu ^ k0 ^ k1;
    x0 += ks0; x1 += ks1;
#define TF_R(rr) { x0 += x1; x1 = (x1 << (rr)) | (x1 >> (32 - (rr))); x1 ^= x0; }
    TF_R(13) TF_R(15) TF_R(26) TF_R(6)  x0 += ks1; x1 += ks2 + 1u;
    TF_R(17) TF_R(29) TF_R(16) TF_R(24) x0 += ks2; x1 += ks0 + 2u;
    TF_R(13) TF_R(15) TF_R(26) TF_R(6)  x0 += ks0; x1 += ks1 + 3u;
    TF_R(17) TF_R(29) TF_R(16) TF_R(24) x0 += ks1; x1 += ks2 + 4u;
    TF_R(13) TF_R(15) TF_R(26) TF_R(6)  x0 += ks2; x1 += ks0 + 5u;
#undef TF_R
    o0 = x0; o1 = x1;
}

// ---------------- launch 3: relu + dropout mask + bf16 hi/lo split ----------------
__global__ __launch_bounds__(256) void k3_mask(const float* __restrict__ bias) {
    int i = blockIdx.x * 256 + threadIdx.x;
    uint32_t o0, o1;
    threefry2x32(0u, 42u, 0u, (uint32_t)i, o0, o1);
    uint32_t bits = o0 ^ o1;
    float u = __uint_as_float((bits >> 9) | 0x3f800000u) - 1.0f;
    float v = g_agg[i] + bias[i & 63];
    v = fmaxf(v, 0.0f);
    float y = (u < 0.7f) ? (v / 0.7f) : 0.0f;
    __nv_bfloat16 hi = __float2bfloat16(y);
    g_xhi[i] = hi;
    g_xlo[i] = __float2bfloat16(y - __bfloat162float(hi));
}

// ---------------- launch 4: out = x @ x^T (champion, unchanged from R15) -------------
#define SM_AHI  0
#define SM_ALO  8192
#define SM_BHI  16384
#define SM_BLO  24576
#define SM_TOTAL 32768
#define STG_S 68

__global__ __launch_bounds__(128, 7)
void k4_gemm(float* __restrict__ out) {
    extern __shared__ char smem[];
    uint32_t sb = (uint32_t)__cvta_generic_to_shared(smem);
    int tid = threadIdx.x, wid = tid >> 5, lid = tid & 31;
    int wm = wid & 1, wn = wid >> 1;

    int bid = blockIdx.x;
    int ci = (int)((513.0 - sqrt(513.0 * 513.0 - 8.0 * (double)bid)) * 0.5);
    if (ci < 0) ci = 0;
    if (ci > 255) ci = 255;
    while (ci < 255 && (ci + 1) * (513 - (ci + 1)) / 2 <= bid) ci++;
    while (ci > 0 && ci * (513 - ci) / 2 > bid) ci--;
    int cj = ci + (bid - ci * (513 - ci) / 2);
    int rowA = ci << 6;
    int colB = cj << 6;

    {
        const char* pAh = (const char*)(g_xhi + (size_t)rowA * OUT_F);
        const char* pAl = (const char*)(g_xlo + (size_t)rowA * OUT_F);
        const char* pBh = (const char*)(g_xhi + (size_t)colB * OUT_F);
        const char* pBl = (const char*)(g_xlo + (size_t)colB * OUT_F);
        #pragma unroll
        for (int j = 0; j < 4; j++) {
            int idx = tid + j * 128;
            uint32_t bo = (uint32_t)(idx << 4);
            uint32_t sw = bo ^ ((bo >> 3) & 0x70);
            cp_async16(sb + SM_AHI + sw, pAh + ((size_t)idx << 4));
            cp_async16(sb + SM_ALO + sw, pAl + ((size_t)idx << 4));
            cp_async16(sb + SM_BHI + sw, pBh + ((size_t)idx << 4));
            cp_async16(sb + SM_BLO + sw, pBl + ((size_t)idx << 4));
        }
        asm volatile("cp.async.commit_group;" ::: "memory");
        asm volatile("cp.async.wait_group 0;" ::: "memory");
    }
    __syncthreads();

    float acc[2][4][4];
    #pragma unroll
    for (int mt = 0; mt < 2; mt++)
        #pragma unroll
        for (int nt = 0; nt < 4; nt++)
            #pragma unroll
            for (int e = 0; e < 4; e++) acc[mt][nt][e] = 0.f;

    int lrow = lid & 15, lchk = lid >> 4, lswz = lid & 7;

    #pragma unroll
    for (int kc = 0; kc < 4; kc++) {
        uint32_t chunk = (uint32_t)(((2 * kc + lchk) ^ lswz) << 4);
        uint32_t ah[2][4], al[2][4];
        #pragma unroll
        for (int mt = 0; mt < 2; mt++) {
            uint32_t ro = (uint32_t)((wm * 32 + mt * 16 + lrow) * 128) + chunk;
            ldsm_x4(ah[mt], sb + SM_AHI + ro);
            ldsm_x4(al[mt], sb + SM_ALO + ro);
        }
        #pragma unroll
        for (int np = 0; np < 2; np++) {
            uint32_t bh[4], bl[4];
            uint32_t ro = (uint32_t)((wn * 32 + np * 16 + lrow) * 128) + chunk;
            ldsm_x4(bh, sb + SM_BHI + ro);
            ldsm_x4(bl, sb + SM_BLO + ro);
            #pragma unroll
            for (int mt = 0; mt < 2; mt++)
                #pragma unroll
                for (int sel = 0; sel < 2; sel++) {
                    int nt = np * 2 + sel;
                    mma16816(acc[mt][nt], ah[mt], bh[sel], bh[sel + 2]);
                    mma16816(acc[mt][nt], ah[mt], bl[sel], bl[sel + 2]);
                    mma16816(acc[mt][nt], al[mt], bh[sel], bh[sel + 2]);
                }
        }
    }
    __syncthreads();

    float* stage = (float*)smem;
    int gid = lid >> 2, tig = lid & 3;

    #pragma unroll
    for (int mt = 0; mt < 2; mt++)
        #pragma unroll
        for (int half = 0; half < 2; half++) {
            int r = wm * 32 + mt * 16 + gid + 8 * half;
            #pragma unroll
            for (int nt = 0; nt < 4; nt++) {
                int c = wn * 32 + nt * 8 + tig * 2;
                *(float2*)&stage[r * STG_S + c] =
                    make_float2(acc[mt][nt][half * 2], acc[mt][nt][half * 2 + 1]);
            }
        }
    __syncthreads();
    if (tid < 64) {
        asm volatile("fence.proxy.async.shared::cta;" ::: "memory");
        bulk_store(out + (size_t)(rowA + tid) * 16384 + colB,
                   sb + (uint32_t)(tid * STG_S * 4), 256u);
        asm volatile("cp.async.bulk.commit_group;" ::: "memory");
    }

    if (ci != cj) {
        if (tid < 64)
            asm volatile("cp.async.bulk.wait_group 0;" ::: "memory");
        __syncthreads();
        #pragma unroll
        for (int mt = 0; mt < 2; mt++)
            #pragma unroll
            for (int half = 0; half < 2; half++) {
                int r = wm * 32 + mt * 16 + gid + 8 * half;
                #pragma unroll
                for (int nt = 0; nt < 4; nt++) {
                    int c = wn * 32 + nt * 8 + tig * 2;
                    stage[c * STG_S + r]       = acc[mt][nt][half * 2];
                    stage[(c + 1) * STG_S + r] = acc[mt][nt][half * 2 + 1];
                }
            }
        __syncthreads();
        if (tid < 64) {
            asm volatile("fence.proxy.async.shared::cta;" ::: "memory");
            bulk_store(out + (size_t)(colB + tid) * 16384 + rowA,
                       sb + (uint32_t)(tid * STG_S * 4), 256u);
            asm volatile("cp.async.bulk.commit_group;" ::: "memory");
        }
    }

    if (tid < 64)
        asm volatile("cp.async.bulk.wait_group 0;" ::: "memory");
}

// ---------------- launch ----------------
extern "C" void kernel_launch(void* const* d_in, const int* in_sizes, int n_in,
                              void* d_out, int out_size) {
    const float*        h    = (const float*)d_in[0];
    const unsigned int* srcw = (const unsigned int*)d_in[1];
    const unsigned int* dstw = (const unsigned int*)d_in[2];
    const float*        W    = (const float*)d_in[3];
    const float*        bias = (const float*)d_in[4];
    float*              out  = (float*)d_out;

    cudaFuncSetAttribute(k_fused1, cudaFuncAttributeMaxDynamicSharedMemorySize, PJ_SMEM);
    k_fused1<<<2305, 128, PJ_SMEM>>>(h, W, srcw);           // 1
    k2_scatter<<<(NE / 4 * 16) / 256, 256>>>(srcw, dstw);   // 2
    k3_mask<<<(N_NODES * OUT_F) / 256, 256>>>(bias);        // 3

    cudaFuncSetAttribute(k4_gemm, cudaFuncAttributeMaxDynamicSharedMemorySize, SM_TOTAL);
    k4_gemm<<<N_TILES, 128, SM_TOTAL>>>(out);               // 4 (ncu target)
}

// round 17
// speedup vs baseline: 1.0642x; 1.0023x over previous
#include <cuda_runtime.h>
#include <cuda_bf16.h>
#include <stdint.h>

// ---------------- problem constants ----------------
#define N_NODES 16384
#define NE      524288
#define IN_F    128
#define OUT_F   64
#define NB      256                       // 64-row blocks
#define N_TILES ((NB * (NB + 1)) / 2)     // 32896 triangular 64x64 tiles

// ---------------- device scratch ----------------
__device__ float         g_hw [N_NODES * OUT_F];   // 4 MB
__device__ float         g_agg[N_NODES * OUT_F];   // 4 MB
__device__ __nv_bfloat16 g_xhi[N_NODES * OUT_F];   // 2 MB
__device__ __nv_bfloat16 g_xlo[N_NODES * OUT_F];   // 2 MB
__device__ int           g_is64;

// ---------------- shared mma helpers ----------------
__device__ __forceinline__ void ldsm_x4(uint32_t* r, uint32_t addr) {
    asm volatile("ldmatrix.sync.aligned.m8n8.x4.shared.b16 {%0,%1,%2,%3}, [%4];"
                 : "=r"(r[0]), "=r"(r[1]), "=r"(r[2]), "=r"(r[3]) : "r"(addr));
}
__device__ __forceinline__ void mma16816(float* d, const uint32_t* a,
                                         uint32_t b0, uint32_t b1) {
    asm volatile(
        "mma.sync.aligned.m16n8k16.row.col.f32.bf16.bf16.f32 "
        "{%0,%1,%2,%3}, {%4,%5,%6,%7}, {%8,%9}, {%0,%1,%2,%3};"
        : "+f"(d[0]), "+f"(d[1]), "+f"(d[2]), "+f"(d[3])
        : "r"(a[0]), "r"(a[1]), "r"(a[2]), "r"(a[3]), "r"(b0), "r"(b1));
}
__device__ __forceinline__ void cp_async16(uint32_t saddr, const void* gptr) {
    asm volatile("cp.async.cg.shared.global [%0], [%1], 16;"
                 :: "r"(saddr), "l"(gptr) : "memory");
}
__device__ __forceinline__ void bulk_store(void* gptr, uint32_t saddr, unsigned bytes) {
    asm volatile("cp.async.bulk.global.shared::cta.bulk_group [%0], [%1], %2;"
                 :: "l"(gptr), "r"(saddr), "r"(bytes) : "memory");
}

// ---------------- launch 1: fused tensor-proj + zero(agg) + detect ----------------
// bids [0,256): proj 64-row tiles via bf16 hi/lo mma (3 products, err ~2^-16)
// bids [256,2304): zero g_agg (512 floats/thread-block of 128 via float4)
// bid 2304: int-width detect
// smem: sAhi(16K) sAlo(16K) sBhi(16K) sBlo(16K); each = 2 slabs of [64 rows][128 B]
#define PJ_AHI 0
#define PJ_ALO 16384
#define PJ_BHI 32768
#define PJ_BLO 49152
#define PJ_SMEM 65536

__global__ __launch_bounds__(128) void k_fused1(const float* __restrict__ h,
                                                const float* __restrict__ W,
                                                const unsigned int* __restrict__ srcw) {
    int bid = blockIdx.x;
    int tid = threadIdx.x;
    if (bid >= 256) {
        if (bid < 2304) {
            int i = ((bid - 256) * 128 + tid) * 4;
            *(float4*)&g_agg[i] = make_float4(0.f, 0.f, 0.f, 0.f);
        } else {
            __shared__ int cnt;
            if (tid == 0) cnt = 0;
            __syncthreads();
            int z = 0;
            for (int i = tid; i < 1024; i += 128)
                z += (srcw[2 * i + 1] == 0u) ? 1 : 0;
            atomicAdd(&cnt, z);
            __syncthreads();
            if (tid == 0) g_is64 = (cnt > 512) ? 1 : 0;
            return;
        }
        return;
    }

    extern __shared__ char smem[];
    uint32_t sb = (uint32_t)__cvta_generic_to_shared(smem);
    int wid = tid >> 5, lid = tid & 31;
    int wm = wid & 1, wn = wid >> 1;       // 2x2 warp grid; warp tile 32 rows x 32 cols
    int row0 = bid * 64;

    // ---- stage h rows (64 x 128 fp32) as bf16 hi/lo, 2-slab SW128 ----
    {
        // 8192 elements, 64 per thread (float4 chunks: 2048 total, 16/thread)
        const float4* hp = (const float4*)(h + (size_t)row0 * IN_F);
        #pragma unroll
        for (int j = 0; j < 16; j++) {
            int ci = tid + j * 128;          // float4 index; 32 per row
            float4 v = hp[ci];
            int r = ci >> 5, k4i = (ci & 31) << 2;
            #pragma unroll
            for (int e = 0; e < 4; e++) {
                float f = (&v.x)[e];
                int k = k4i + e;
                __nv_bfloat16 hi = __float2bfloat16(f);
                __nv_bfloat16 lo = __float2bfloat16(f - __bfloat162float(hi));
                uint32_t off = (uint32_t)((k >> 6) * 8192 + r * 128 + (k & 63) * 2);
                uint32_t sw = off ^ ((off >> 3) & 0x70);
                *(__nv_bfloat16*)(smem + PJ_AHI + sw) = hi;
                *(__nv_bfloat16*)(smem + PJ_ALO + sw) = lo;
            }
        }
        // W [128k x 64n] -> B operand [n rows][k cols], bf16 hi/lo, same layout
        const float4* wp = (const float4*)W;
        #pragma unroll
        for (int j = 0; j < 16; j++) {
            int ci = tid + j * 128;          // float4 index; 16 per k-row
            float4 v = wp[ci];
            int k = ci >> 4, n4 = (ci & 15) << 2;
            #pragma unroll
            for (int e = 0; e < 4; e++) {
                float f = (&v.x)[e];
                int n = n4 + e;
                __nv_bfloat16 hi = __float2bfloat16(f);
                __nv_bfloat16 lo = __float2bfloat16(f - __bfloat162float(hi));
                uint32_t off = (uint32_t)((k >> 6) * 8192 + n * 128 + (k & 63) * 2);
                uint32_t sw = off ^ ((off >> 3) & 0x70);
                *(__nv_bfloat16*)(smem + PJ_BHI + sw) = hi;
                *(__nv_bfloat16*)(smem + PJ_BLO + sw) = lo;
            }
        }
    }
    __syncthreads();

    float acc[2][4][4];
    #pragma unroll
    for (int mt = 0; mt < 2; mt++)
        #pragma unroll
        for (int nt = 0; nt < 4; nt++)
            #pragma unroll
            for (int e = 0; e < 4; e++) acc[mt][nt][e] = 0.f;

    int lrow = lid & 15, lchk = lid >> 4, lswz = lid & 7;

    #pragma unroll
    for (int kc = 0; kc < 8; kc++) {
        uint32_t slab = (uint32_t)((kc >> 2) * 8192);
        uint32_t chunk = (uint32_t)(((2 * (kc & 3) + lchk) ^ lswz) << 4) + slab;
        uint32_t ah[2][4], al[2][4];
        #pragma unroll
        for (int mt = 0; mt < 2; mt++) {
            uint32_t ro = (uint32_t)((wm * 32 + mt * 16 + lrow) * 128) + chunk;
            ldsm_x4(ah[mt], sb + PJ_AHI + ro);
            ldsm_x4(al[mt], sb + PJ_ALO + ro);
        }
        #pragma unroll
        for (int np = 0; np < 2; np++) {
            uint32_t bh[4], bl[4];
            uint32_t ro = (uint32_t)((wn * 32 + np * 16 + lrow) * 128) + chunk;
            ldsm_x4(bh, sb + PJ_BHI + ro);
            ldsm_x4(bl, sb + PJ_BLO + ro);
            #pragma unroll
            for (int mt = 0; mt < 2; mt++)
                #pragma unroll
                for (int sel = 0; sel < 2; sel++) {
                    int nt = np * 2 + sel;
                    mma16816(acc[mt][nt], ah[mt], bh[sel], bh[sel + 2]); // hi*hi
                    mma16816(acc[mt][nt], ah[mt], bl[sel], bl[sel + 2]); // hi*lo
                    mma16816(acc[mt][nt], al[mt], bh[sel], bh[sel + 2]); // lo*hi
                }
        }
    }

    // direct store of hw fragments (float2 per fragment pair)
    int gid = lid >> 2, tig = lid & 3;
    #pragma unroll
    for (int mt = 0; mt < 2; mt++)
        #pragma unroll
        for (int half = 0; half < 2; half++) {
            int r = wm * 32 + mt * 16 + gid + 8 * half;
            #pragma unroll
            for (int nt = 0; nt < 4; nt++) {
                int c = wn * 32 + nt * 8 + tig * 2;
                *(float2*)&g_hw[(size_t)(row0 + r) * OUT_F + c] =
                    make_float2(acc[mt][nt][half * 2], acc[mt][nt][half * 2 + 1]);
            }
        }
}

// ---------------- launch 2: scatter, 4 edges per 16-lane group (MLP=4) ----------------
__global__ __launch_bounds__(256) void k2_scatter(const unsigned int* __restrict__ srcw,
                                                  const unsigned int* __restrict__ dstw) {
    unsigned g = (blockIdx.x * 256u + threadIdx.x) >> 4;   // quad id < NE/4
    int sub = threadIdx.x & 15;
    unsigned s[4], d[4];
    if (!g_is64) {
        uint4 sv = *(const uint4*)&srcw[4 * (size_t)g];
        uint4 dv = *(const uint4*)&dstw[4 * (size_t)g];
        s[0] = sv.x; s[1] = sv.y; s[2] = sv.z; s[3] = sv.w;
        d[0] = dv.x; d[1] = dv.y; d[2] = dv.z; d[3] = dv.w;
    } else {
        uint4 sv0 = *(const uint4*)&srcw[8 * (size_t)g];
        uint4 sv1 = *(const uint4*)&srcw[8 * (size_t)g + 4];
        uint4 dv0 = *(const uint4*)&dstw[8 * (size_t)g];
        uint4 dv1 = *(const uint4*)&dstw[8 * (size_t)g + 4];
        s[0] = sv0.x; s[1] = sv0.z; s[2] = sv1.x; s[3] = sv1.z;
        d[0] = dv0.x; d[1] = dv0.z; d[2] = dv1.x; d[3] = dv1.z;
    }
    const float4* src = (const float4*)g_hw;
    float4 v[4];
    #pragma unroll
    for (int i = 0; i < 4; i++) v[i] = src[s[i] * 16 + sub];
    #pragma unroll
    for (int i = 0; i < 4; i++)
        asm volatile("red.global.add.v4.f32 [%0], {%1,%2,%3,%4};"
                     :: "l"(&g_agg[d[i] * OUT_F + sub * 4]),
                        "f"(v[i].x), "f"(v[i].y), "f"(v[i].z), "f"(v[i].w) : "memory");
}

// ---------------- threefry2x32 (JAX-exact, 20 rounds) ----------------
__device__ __forceinline__ void threefry2x32(uint32_t k0, uint32_t k1,
                                             uint32_t x0, uint32_t x1,
                                             uint32_t& o0, uint32_t& o1) {
    uint32_t ks0 = k0, ks1 = k1, ks2 = 0x1BD11BDAu ^ k0 ^ k1;
    x0 += ks0; x1 += ks1;
#define TF_R(rr) { x0 += x1; x1 = (x1 << (rr)) | (x1 >> (32 - (rr))); x1 ^= x0; }
    TF_R(13) TF_R(15) TF_R(26) TF_R(6)  x0 += ks1; x1 += ks2 + 1u;
    TF_R(17) TF_R(29) TF_R(16) TF_R(24) x0 += ks2; x1 += ks0 + 2u;
    TF_R(13) TF_R(15) TF_R(26) TF_R(6)  x0 += ks0; x1 += ks1 + 3u;
    TF_R(17) TF_R(29) TF_R(16) TF_R(24) x0 += ks1; x1 += ks2 + 4u;
    TF_R(13) TF_R(15) TF_R(26) TF_R(6)  x0 += ks2; x1 += ks0 + 5u;
#undef TF_R
    o0 = x0; o1 = x1;
}

// ---------------- launch 3: relu + dropout mask + bf16 hi/lo split ----------------
__global__ __launch_bounds__(256) void k3_mask(const float* __restrict__ bias) {
    int i = blockIdx.x * 256 + threadIdx.x;
    uint32_t o0, o1;
    threefry2x32(0u, 42u, 0u, (uint32_t)i, o0, o1);
    uint32_t bits = o0 ^ o1;
    float u = __uint_as_float((bits >> 9) | 0x3f800000u) - 1.0f;
    float v = g_agg[i] + bias[i & 63];
    v = fmaxf(v, 0.0f);
    float y = (u < 0.7f) ? (v / 0.7f) : 0.0f;
    __nv_bfloat16 hi = __float2bfloat16(y);
    g_xhi[i] = hi;
    g_xlo[i] = __float2bfloat16(y - __bfloat162float(hi));
}

// ---------------- launch 4: out = x @ x^T (champion, unchanged from R15) -------------
#define SM_AHI  0
#define SM_ALO  8192
#define SM_BHI  16384
#define SM_BLO  24576
#define SM_TOTAL 32768
#define STG_S 68

__global__ __launch_bounds__(128, 7)
void k4_gemm(float* __restrict__ out) {
    extern __shared__ char smem[];
    uint32_t sb = (uint32_t)__cvta_generic_to_shared(smem);
    int tid = threadIdx.x, wid = tid >> 5, lid = tid & 31;
    int wm = wid & 1, wn = wid >> 1;

    int bid = blockIdx.x;
    int ci = (int)((513.0 - sqrt(513.0 * 513.0 - 8.0 * (double)bid)) * 0.5);
    if (ci < 0) ci = 0;
    if (ci > 255) ci = 255;
    while (ci < 255 && (ci + 1) * (513 - (ci + 1)) / 2 <= bid) ci++;
    while (ci > 0 && ci * (513 - ci) / 2 > bid) ci--;
    int cj = ci + (bid - ci * (513 - ci) / 2);
    int rowA = ci << 6;
    int colB = cj << 6;

    {
        const char* pAh = (const char*)(g_xhi + (size_t)rowA * OUT_F);
        const char* pAl = (const char*)(g_xlo + (size_t)rowA * OUT_F);
        const char* pBh = (const char*)(g_xhi + (size_t)colB * OUT_F);
        const char* pBl = (const char*)(g_xlo + (size_t)colB * OUT_F);
        #pragma unroll
        for (int j = 0; j < 4; j++) {
            int idx = tid + j * 128;
            uint32_t bo = (uint32_t)(idx << 4);
            uint32_t sw = bo ^ ((bo >> 3) & 0x70);
            cp_async16(sb + SM_AHI + sw, pAh + ((size_t)idx << 4));
            cp_async16(sb + SM_ALO + sw, pAl + ((size_t)idx << 4));
            cp_async16(sb + SM_BHI + sw, pBh + ((size_t)idx << 4));
            cp_async16(sb + SM_BLO + sw, pBl + ((size_t)idx << 4));
        }
        asm volatile("cp.async.commit_group;" ::: "memory");
        asm volatile("cp.async.wait_group 0;" ::: "memory");
    }
    __syncthreads();

    float acc[2][4][4];
    #pragma unroll
    for (int mt = 0; mt < 2; mt++)
        #pragma unroll
        for (int nt = 0; nt < 4; nt++)
            #pragma unroll
            for (int e = 0; e < 4; e++) acc[mt][nt][e] = 0.f;

    int lrow = lid & 15, lchk = lid >> 4, lswz = lid & 7;

    #pragma unroll
    for (int kc = 0; kc < 4; kc++) {
        uint32_t chunk = (uint32_t)(((2 * kc + lchk) ^ lswz) << 4);
        uint32_t ah[2][4], al[2][4];
        #pragma unroll
        for (int mt = 0; mt < 2; mt++) {
            uint32_t ro = (uint32_t)((wm * 32 + mt * 16 + lrow) * 128) + chunk;
            ldsm_x4(ah[mt], sb + SM_AHI + ro);
            ldsm_x4(al[mt], sb + SM_ALO + ro);
        }
        #pragma unroll
        for (int np = 0; np < 2; np++) {
            uint32_t bh[4], bl[4];
            uint32_t ro = (uint32_t)((wn * 32 + np * 16 + lrow) * 128) + chunk;
            ldsm_x4(bh, sb + SM_BHI + ro);
            ldsm_x4(bl, sb + SM_BLO + ro);
            #pragma unroll
            for (int mt = 0; mt < 2; mt++)
                #pragma unroll
                for (int sel = 0; sel < 2; sel++) {
                    int nt = np * 2 + sel;
                    mma16816(acc[mt][nt], ah[mt], bh[sel], bh[sel + 2]);
                    mma16816(acc[mt][nt], ah[mt], bl[sel], bl[sel + 2]);
                    mma16816(acc[mt][nt], al[mt], bh[sel], bh[sel + 2]);
                }
        }
    }
    __syncthreads();

    float* stage = (float*)smem;
    int gid = lid >> 2, tig = lid & 3;

    #pragma unroll
    for (int mt = 0; mt < 2; mt++)
        #pragma unroll
        for (int half = 0; half < 2; half++) {
            int r = wm * 32 + mt * 16 + gid + 8 * half;
            #pragma unroll
            for (int nt = 0; nt < 4; nt++) {
                int c = wn * 32 + nt * 8 + tig * 2;
                *(float2*)&stage[r * STG_S + c] =
                    make_float2(acc[mt][nt][half * 2], acc[mt][nt][half * 2 + 1]);
            }
        }
    __syncthreads();
    if (tid < 64) {
        asm volatile("fence.proxy.async.shared::cta;" ::: "memory");
        bulk_store(out + (size_t)(rowA + tid) * 16384 + colB,
                   sb + (uint32_t)(tid * STG_S * 4), 256u);
        asm volatile("cp.async.bulk.commit_group;" ::: "memory");
    }

    if (ci != cj) {
        if (tid < 64)
            asm volatile("cp.async.bulk.wait_group 0;" ::: "memory");
        __syncthreads();
        #pragma unroll
        for (int mt = 0; mt < 2; mt++)
            #pragma unroll
            for (int half = 0; half < 2; half++) {
                int r = wm * 32 + mt * 16 + gid + 8 * half;
                #pragma unroll
                for (int nt = 0; nt < 4; nt++) {
                    int c = wn * 32 + nt * 8 + tig * 2;
                    stage[c * STG_S + r]       = acc[mt][nt][half * 2];
                    stage[(c + 1) * STG_S + r] = acc[mt][nt][half * 2 + 1];
                }
            }
        __syncthreads();
        if (tid < 64) {
            asm volatile("fence.proxy.async.shared::cta;" ::: "memory");
            bulk_store(out + (size_t)(colB + tid) * 16384 + rowA,
                       sb + (uint32_t)(tid * STG_S * 4), 256u);
            asm volatile("cp.async.bulk.commit_group;" ::: "memory");
        }
    }

    if (tid < 64)
        asm volatile("cp.async.bulk.wait_group 0;" ::: "memory");
}

// ---------------- launch ----------------
extern "C" void kernel_launch(void* const* d_in, const int* in_sizes, int n_in,
                              void* d_out, int out_size) {
    const float*        h    = (const float*)d_in[0];
    const unsigned int* srcw = (const unsigned int*)d_in[1];
    const unsigned int* dstw = (const unsigned int*)d_in[2];
    const float*        W    = (const float*)d_in[3];
    const float*        bias = (const float*)d_in[4];
    float*              out  = (float*)d_out;

    cudaFuncSetAttribute(k_fused1, cudaFuncAttributeMaxDynamicSharedMemorySize, PJ_SMEM);
    k_fused1<<<2305, 128, PJ_SMEM>>>(h, W, srcw);           // 1
    k2_scatter<<<(NE / 4 * 16) / 256, 256>>>(srcw, dstw);   // 2
    k3_mask<<<(N_NODES * OUT_F) / 256, 256>>>(bias);        // 3

    cudaFuncSetAttribute(k4_gemm, cudaFuncAttributeMaxDynamicSharedMemorySize, SM_TOTAL);
    k4_gemm<<<N_TILES, 128, SM_TOTAL>>>(out);               // 4 (ncu target)
}